// round 11
// baseline (speedup 1.0000x reference)
#include <cuda_runtime.h>
#include <cuda_bf16.h>
#include <cstdint>

#define T_FRAMES 16384
#define E_DIM    1024
#define M_MODELS 8
#define K_CLUST  512

#define TM   64             // frames per CTA tile
#define TN   512
#define KBLK 128            // K elements per stage (128B rows)
#define NSTAGE (E_DIM / KBLK)   // 8
#define MAXT_G 40
#define NTHREADS 1024
#define TAU  20.0f
#define CAP  2048

#define STAGE_BYTES 65536   // 32KB fp8-B (rows 0-255) + 32KB dp4a-B (cols 256-511)

// ---- persistent scratch ----
// per (m, stage): [0,32768) fp8 rows 0-255 swizzled; [32768,65536) s8 [chunk][col] cols 256-511
__device__ uint8_t g_cent_pack[M_MODELS * NSTAGE * STAGE_BYTES];   // 4.2MB
__device__ int   g_counts[M_MODELS];
__device__ int   g_rows[M_MODELS * T_FRAMES];
__device__ float g_chalf[M_MODELS * K_CLUST];

// ================= helpers =================
__device__ __forceinline__ uint32_t smem_u32(const void* p) {
    uint32_t a;
    asm("{ .reg .u64 t; cvta.to.shared.u64 t, %1; cvt.u32.u64 %0, t; }" : "=r"(a) : "l"(p));
    return a;
}
__device__ __forceinline__ void bulk_g2s(uint32_t dst, const void* src,
                                         uint32_t bytes, uint32_t mbar) {
    asm volatile(
        "cp.async.bulk.shared::cluster.global.mbarrier::complete_tx::bytes [%0], [%1], %2, [%3];"
        :: "r"(dst), "l"(src), "r"(bytes), "r"(mbar) : "memory");
}
#define MBARRIER_INIT(addr, cnt) \
    asm volatile("mbarrier.init.shared.b64 [%0], %1;" :: "r"((uint32_t)(addr)), "r"((uint32_t)(cnt)) : "memory")
#define MBARRIER_EXPECT_TX(addr, bytes) \
    asm volatile("mbarrier.arrive.expect_tx.shared.b64 _, [%0], %1;" \
                 :: "r"((uint32_t)(addr)), "r"((uint32_t)(bytes)) : "memory")
#define MBARRIER_WAIT_PARITY(addr, par) do { \
    uint32_t _mb = (uint32_t)(addr); uint32_t _pr = (uint32_t)(par); uint32_t _done; \
    asm volatile("{\n\t.reg .pred p;\n\t" \
        "mbarrier.try_wait.parity.acquire.cta.shared::cta.b64 p, [%1], %2;\n\t" \
        "selp.b32 %0, 1, 0, p;\n\t}" : "=r"(_done) : "r"(_mb), "r"(_pr) : "memory"); \
    if (!_done) { \
        asm volatile("{\n\t.reg .pred P1;\n\t" \
            "WL_%=:\n\t" \
            "mbarrier.try_wait.parity.acquire.cta.shared::cta.b64 P1, [%0], %1, 0x989680;\n\t" \
            "@P1 bra.uni WD_%=;\n\t" \
            "bra.uni WL_%=;\n\t" \
            "WD_%=:\n\t}" :: "r"(_mb), "r"(_pr) : "memory"); \
    } } while (0)
__device__ __forceinline__ void ldmx4(uint32_t addr, uint32_t& r0, uint32_t& r1,
                                      uint32_t& r2, uint32_t& r3) {
    asm volatile("ldmatrix.sync.aligned.m8n8.x4.shared.b16 {%0,%1,%2,%3}, [%4];"
                 : "=r"(r0), "=r"(r1), "=r"(r2), "=r"(r3) : "r"(addr));
}
__device__ __forceinline__ void mma_fp8(float* c, uint32_t a0, uint32_t a1,
                                        uint32_t a2, uint32_t a3,
                                        uint32_t b0, uint32_t b1) {
    asm volatile(
        "mma.sync.aligned.m16n8k32.row.col.f32.e4m3.e4m3.f32 "
        "{%0,%1,%2,%3}, {%4,%5,%6,%7}, {%8,%9}, {%0,%1,%2,%3};"
        : "+f"(c[0]), "+f"(c[1]), "+f"(c[2]), "+f"(c[3])
        : "r"(a0), "r"(a1), "r"(a2), "r"(a3), "r"(b0), "r"(b1));
}
__device__ __forceinline__ void dp4a(int& acc, uint32_t a, uint32_t b) {
    asm volatile("dp4a.s32.s32 %0, %1, %2, %0;" : "+r"(acc) : "r"(a), "r"(b));
}
__device__ __forceinline__ unsigned int fkey(float f) {
    unsigned u = __float_as_uint(f);
    return (u & 0x80000000u) ? ~u : (u | 0x80000000u);
}
__device__ __forceinline__ float inv_fkey(unsigned k) {
    unsigned u = (k & 0x80000000u) ? (k & 0x7FFFFFFFu) : ~k;
    return __uint_as_float(u);
}
__device__ __forceinline__ uint32_t f4_to_fp8(float4 v) {
    uint32_t p;
    asm("{ .reg .b16 lo, hi;\n\t"
        "cvt.rn.satfinite.e4m3x2.f32 lo, %2, %1;\n\t"
        "cvt.rn.satfinite.e4m3x2.f32 hi, %4, %3;\n\t"
        "mov.b32 %0, {lo, hi}; }"
        : "=r"(p) : "f"(v.x), "f"(v.y), "f"(v.z), "f"(v.w));
    return p;
}
__device__ __forceinline__ uint32_t f4_to_s8(float4 v) {
    int a = __float2int_rn(fminf(fmaxf(v.x * 16.f, -127.f), 127.f));
    int b = __float2int_rn(fminf(fmaxf(v.y * 16.f, -127.f), 127.f));
    int c = __float2int_rn(fminf(fmaxf(v.z * 16.f, -127.f), 127.f));
    int d = __float2int_rn(fminf(fmaxf(v.w * 16.f, -127.f), 127.f));
    return (a & 255) | ((b & 255) << 8) | ((c & 255) << 16) | ((d & 255) << 24);
}

// ================= smem layout (bytes) =================
#define SM_B      0                        // 2 x 64KB: [mma 32KB | dp 32KB]
#define SM_A8     131072                   // 2 x 8KB fp8 swizzled
#define SM_AS8    147456                   // 2 x 8KB s8 linear
#define SM_CHALF  163840                   // 512 f32
#define SM_ROWIDX 165888                   // 64 int
#define SM_THR    166144                   // 64 f32
#define SM_PMIN   166400                   // 64 u32 (fkey)
#define SM_BEST   166656                   // 64 u64
#define SM_MBAR   167168                   // 2 x 8B
#define SM_CNT    167184                   // int (+pad)
#define SM_CODE   167200                   // 64 int
#define SM_CAND   167456                   // CAP ints
#define SMEM_TOTAL (167456 + CAP * 4 + 32) // ~171.5KB -> 1 CTA/SM

// ================= prep kernels =================
__global__ void init_kernel() {
    int t = threadIdx.x;
    if (t < M_MODELS) g_counts[t] = 0;
}

__global__ void bucket_kernel(const int* __restrict__ model_idx) {
    int t = blockIdx.x * blockDim.x + threadIdx.x;
    if (t >= T_FRAMES) return;
    int m = model_idx[t];
    int pos = atomicAdd(&g_counts[m], 1);
    g_rows[m * T_FRAMES + pos] = t;
}

// one warp per centroid row: build packed dual-format B + chalf in one read
__global__ void prep_cent_kernel(const float* __restrict__ cent) {
    int warp = (blockIdx.x * blockDim.x + threadIdx.x) >> 5;
    int lane = threadIdx.x & 31;
    if (warp >= M_MODELS * K_CLUST) return;
    const int m = warp >> 9;
    const int r = warp & 511;
    const float4* src = reinterpret_cast<const float4*>(cent + (size_t)warp * E_DIM);
    float s = 0.f;
    #pragma unroll
    for (int q = 0; q < NSTAGE; ++q) {     // q == stage, lane == 16B/chunk slot
        float4 v = src[lane + 32 * q];
        uint8_t* base = g_cent_pack + ((size_t)(m * NSTAGE + q)) * STAGE_BYTES;
        if (r < 256) {
            uint32_t off = r * 128 + (((lane >> 2) ^ (r & 7)) << 4) + (lane & 3) * 4;
            *reinterpret_cast<uint32_t*>(base + off) = f4_to_fp8(v);
        } else {
            // dp layout: [chunk 0..31][col 0..255] u32 (s8x4), col = r-256, chunk = lane
            *reinterpret_cast<uint32_t*>(base + 32768 + lane * 1024 + (r - 256) * 4)
                = f4_to_s8(v);
        }
        s += v.x * v.x + v.y * v.y + v.z * v.z + v.w * v.w;
    }
    #pragma unroll
    for (int o = 16; o; o >>= 1) s += __shfl_xor_sync(0xffffffffu, s, o);
    if (lane == 0) g_chalf[warp] = 0.5f * s;
}

// ================= fused hybrid GEMM + argmin + rescore + output =================
__global__ __launch_bounds__(NTHREADS, 1)
void fused_kernel(const float* __restrict__ emb, const float* __restrict__ cent,
                  float* __restrict__ out) {
    extern __shared__ char smem[];
    const uint32_t sb = smem_u32(smem);

    const int m   = blockIdx.x / MAXT_G;
    const int mtb = blockIdx.x % MAXT_G;
    const int cnt = g_counts[m];
    const int ntiles = (cnt + TM - 1) / TM;
    const int* rowsm = g_rows + m * T_FRAMES;

    const int tid  = threadIdx.x;
    const int wid  = tid >> 5;
    const int lane = tid & 31;

    int*   rowidx_s = reinterpret_cast<int*>(smem + SM_ROWIDX);
    float* chalf_s  = reinterpret_cast<float*>(smem + SM_CHALF);
    float* thr_s    = reinterpret_cast<float*>(smem + SM_THR);
    unsigned* pmin_s = reinterpret_cast<unsigned*>(smem + SM_PMIN);
    unsigned long long* best_s = reinterpret_cast<unsigned long long*>(smem + SM_BEST);
    int* cnt_s  = reinterpret_cast<int*>(smem + SM_CNT);
    int* code_s = reinterpret_cast<int*>(smem + SM_CODE);
    int* cand_s = reinterpret_cast<int*>(smem + SM_CAND);

    if (tid < TN) chalf_s[tid] = g_chalf[m * K_CLUST + tid];
    if (tid == 0) {
        MBARRIER_INIT(sb + SM_MBAR, 1);
        MBARRIER_INIT(sb + SM_MBAR + 8, 1);
    }
    __syncthreads();

    const uint8_t* bsrc = g_cent_pack + (size_t)m * NSTAGE * STAGE_BYTES;
    const float4* emb4  = reinterpret_cast<const float4*>(emb);
    const float4* cent4 = reinterpret_cast<const float4*>(cent);

    // A producer plan (all threads): row ar, slot af of 8 floats
    const int ar = tid >> 4, af = tid & 15;
    const uint32_t ad8 = ar * 128 + (((af >> 1) ^ (ar & 7)) << 4) + (af & 1) * 8;
    const uint32_t ads = ar * 128 + af * 8;

    // MMA warp mapping (wid 0..15)
    const int wr = wid >> 2;            // 16-frame row group
    const int wc = wid & 3;             // 64-col group (cols 0-255)
    const int arow_l = wr * 16 + (lane & 7) + ((lane >> 3) & 1) * 8;
    const int brow_l = wc * 64 + (lane & 7) + ((lane >> 3) & 1) * 8;
    const int clane  = lane >> 4;
    const int gid = lane >> 2, tig = lane & 3;

    // dp4a warp mapping (wid 16..31): global lane l -> fg (8 frames), cg (4 cols)
    const int dl = (wid - 16) * 32 + lane;
    const int fg = dl >> 6;             // 0..7  -> frames fg*8..+8
    const int cg = dl & 63;             // 0..63 -> local cols cg*4..+4

    uint32_t par[2] = {0, 0};

    for (int mt = mtb; mt < ntiles; mt += MAXT_G) {
        __syncthreads();
        if (tid < TM) {
            int gr = mt * TM + tid;
            rowidx_s[tid] = rowsm[min(gr, cnt - 1)];
            best_s[tid] = 0xFFFFFFFFFFFFFFFFull;
            pmin_s[tid] = 0xFFFFFFFFu;
        }
        if (tid == 0) cnt_s[0] = 0;
        __syncthreads();

        const float4* aS = emb4 + (size_t)rowidx_s[ar] * 256 + af * 2;

        float accf[8][4];               // MMA accumulators (used by wid<16)
        int   acci[8][4];               // dp4a accumulators (used by wid>=16)
        #pragma unroll
        for (int n = 0; n < 8; ++n)
            #pragma unroll
            for (int r = 0; r < 4; ++r) { accf[n][r] = 0.f; acci[n][r] = 0; }

        if (tid == 0) {
            MBARRIER_EXPECT_TX(sb + SM_MBAR, STAGE_BYTES);
            bulk_g2s(sb + SM_B, bsrc, STAGE_BYTES, sb + SM_MBAR);
        }
        float4 apre0 = aS[0], apre1 = aS[1];

        for (int kb = 0; kb < NSTAGE; ++kb) {
            const int buf = kb & 1;
            // A stores: both formats
            *reinterpret_cast<uint2*>(smem + SM_A8 + buf * 8192 + ad8) =
                make_uint2(f4_to_fp8(apre0), f4_to_fp8(apre1));
            *reinterpret_cast<uint2*>(smem + SM_AS8 + buf * 8192 + ads) =
                make_uint2(f4_to_s8(apre0), f4_to_s8(apre1));
            if (kb + 1 < NSTAGE) {
                const int nb = (kb + 1) & 1;
                if (tid == 0) {
                    MBARRIER_EXPECT_TX(sb + SM_MBAR + 8 * nb, STAGE_BYTES);
                    bulk_g2s(sb + SM_B + nb * STAGE_BYTES,
                             bsrc + (size_t)(kb + 1) * STAGE_BYTES,
                             STAGE_BYTES, sb + SM_MBAR + 8 * nb);
                }
                apre0 = aS[(kb + 1) * 32];
                apre1 = aS[(kb + 1) * 32 + 1];
            }
            MBARRIER_WAIT_PARITY(sb + SM_MBAR + 8 * buf, par[buf]);
            par[buf] ^= 1;
            __syncthreads();

            if (wid < 16) {
                // ---- MMA engine: cols 0-255 ----
                const uint32_t Ab = sb + SM_A8 + buf * 8192;
                const uint32_t Bb = sb + SM_B + buf * STAGE_BYTES;
                #pragma unroll
                for (int ks = 0; ks < 4; ++ks) {
                    const int cc = ks * 2 + clane;
                    uint32_t a0, a1, a2, a3;
                    ldmx4(Ab + arow_l * 128 + ((cc ^ (arow_l & 7)) << 4), a0, a1, a2, a3);
                    #pragma unroll
                    for (int nh = 0; nh < 2; ++nh) {
                        uint32_t b[2][4];
                        #pragma unroll
                        for (int nj = 0; nj < 2; ++nj) {
                            int row = brow_l + nh * 32 + nj * 16;
                            ldmx4(Bb + row * 128 + ((cc ^ (row & 7)) << 4),
                                  b[nj][0], b[nj][1], b[nj][2], b[nj][3]);
                        }
                        #pragma unroll
                        for (int n = 0; n < 4; ++n)
                            mma_fp8(accf[nh * 4 + n], a0, a1, a2, a3,
                                    b[n >> 1][n & 1], b[n >> 1][2 + (n & 1)]);
                    }
                }
            } else {
                // ---- dp4a engine: cols 256-511 ----
                const char* Ab = smem + SM_AS8 + buf * 8192 + fg * 8 * 128;
                const char* Bd = smem + SM_B + buf * STAGE_BYTES + 32768 + cg * 16;
                #pragma unroll 8
                for (int ch = 0; ch < 32; ++ch) {
                    uint4 bv = *reinterpret_cast<const uint4*>(Bd + ch * 1024);
                    uint32_t av[8];
                    #pragma unroll
                    for (int j = 0; j < 8; ++j)     // broadcast loads
                        av[j] = *reinterpret_cast<const uint32_t*>(Ab + j * 128 + ch * 4);
                    #pragma unroll
                    for (int j = 0; j < 8; ++j) {
                        dp4a(acci[j][0], av[j], bv.x);
                        dp4a(acci[j][1], av[j], bv.y);
                        dp4a(acci[j][2], av[j], bv.z);
                        dp4a(acci[j][3], av[j], bv.w);
                    }
                }
            }
            __syncthreads();
        }

        // ---- epilogue 1: per-row min -> pmin_s (fkey atomicMin) ----
        if (wid < 16) {
            float v0 = __int_as_float(0x7F800000), v1 = v0;
            #pragma unroll
            for (int n = 0; n < 8; ++n) {
                int col = wc * 64 + n * 8 + tig * 2;
                float c0 = chalf_s[col], c1 = chalf_s[col + 1];
                v0 = fminf(v0, fminf(c0 - accf[n][0], c1 - accf[n][1]));
                v1 = fminf(v1, fminf(c0 - accf[n][2], c1 - accf[n][3]));
            }
            #pragma unroll
            for (int o = 1; o < 4; o <<= 1) {
                v0 = fminf(v0, __shfl_xor_sync(0xffffffffu, v0, o));
                v1 = fminf(v1, __shfl_xor_sync(0xffffffffu, v1, o));
            }
            if (tig == 0) {
                atomicMin(&pmin_s[wr * 16 + gid], fkey(v0));
                atomicMin(&pmin_s[wr * 16 + gid + 8], fkey(v1));
            }
        } else {
            #pragma unroll
            for (int j = 0; j < 8; ++j) {
                int col = 256 + cg * 4;
                float mv = chalf_s[col] - (float)acci[j][0] * (1.0f / 256.0f);
                #pragma unroll
                for (int k = 1; k < 4; ++k)
                    mv = fminf(mv, chalf_s[col + k] - (float)acci[j][k] * (1.0f / 256.0f));
                #pragma unroll
                for (int o = 16; o; o >>= 1)
                    mv = fminf(mv, __shfl_xor_sync(0xffffffffu, mv, o));
                if (lane == 0) atomicMin(&pmin_s[fg * 8 + j], fkey(mv));
            }
        }
        __syncthreads();
        if (tid < TM) thr_s[tid] = inv_fkey(pmin_s[tid]) + TAU;
        __syncthreads();

        // ---- epilogue 2: collect candidates ----
        if (wid < 16) {
            #pragma unroll
            for (int n = 0; n < 8; ++n) {
                #pragma unroll
                for (int r = 0; r < 4; ++r) {
                    int row = wr * 16 + gid + (r >> 1) * 8;
                    int col = wc * 64 + n * 8 + tig * 2 + (r & 1);
                    float s = chalf_s[col] - accf[n][r];
                    if (s <= thr_s[row]) {
                        int idx = atomicAdd(cnt_s, 1);
                        if (idx < CAP) cand_s[idx] = (row << 16) | col;
                    }
                }
            }
        } else {
            #pragma unroll
            for (int j = 0; j < 8; ++j) {
                int row = fg * 8 + j;
                #pragma unroll
                for (int k = 0; k < 4; ++k) {
                    int col = 256 + cg * 4 + k;
                    float s = chalf_s[col] - (float)acci[j][k] * (1.0f / 256.0f);
                    if (s <= thr_s[row]) {
                        int idx = atomicAdd(cnt_s, 1);
                        if (idx < CAP) cand_s[idx] = (row << 16) | col;
                    }
                }
            }
        }
        __syncthreads();
        const int ncand = min(cnt_s[0], CAP);

        // ---- epilogue 3: exact fp32 rescore (one warp per candidate) ----
        for (int i = wid; i < ncand; i += 32) {
            int rc = cand_s[i];
            int row = rc >> 16, col = rc & 0xFFFF;
            const float4* e4 = emb4 + (size_t)rowidx_s[row] * 256;
            const float4* c4 = cent4 + ((size_t)m * K_CLUST + col) * 256;
            float d = 0.f;
            #pragma unroll
            for (int q = 0; q < 8; ++q) {
                float4 ea = e4[q * 32 + lane];
                float4 ca = c4[q * 32 + lane];
                d += ea.x * ca.x + ea.y * ca.y + ea.z * ca.z + ea.w * ca.w;
            }
            #pragma unroll
            for (int o = 16; o; o >>= 1) d += __shfl_xor_sync(0xffffffffu, d, o);
            if (lane == 0) {
                float s = chalf_s[col] - d;
                unsigned long long key = ((unsigned long long)fkey(s) << 32) | (unsigned)col;
                atomicMin(&best_s[row], key);
            }
        }
        __syncthreads();
        if (tid < TM) code_s[tid] = (int)(unsigned)(best_s[tid] & 0xFFFFFFFFull);
        __syncthreads();

        // ---- epilogue 4: write output rows ----
        float4* out4 = reinterpret_cast<float4*>(out);
        for (int idx = tid; idx < TM * 256; idx += NTHREADS) {
            int r = idx >> 8, q = idx & 255;
            if (mt * TM + r < cnt) {
                int frame = rowidx_s[r];
                out4[(size_t)frame * 256 + q] =
                    cent4[((size_t)m * K_CLUST + code_s[r]) * 256 + q];
            }
        }
    }
}

// ================= launch =================
extern "C" void kernel_launch(void* const* d_in, const int* in_sizes, int n_in,
                              void* d_out, int out_size) {
    const float* emb  = (const float*)d_in[0];
    const float* cent = (const float*)d_in[1];
    const int*   midx = (const int*)d_in[2];
    float* out = (float*)d_out;

    cudaFuncSetAttribute(fused_kernel,
                         cudaFuncAttributeMaxDynamicSharedMemorySize, SMEM_TOTAL);

    init_kernel<<<1, 32>>>();
    bucket_kernel<<<(T_FRAMES + 255) / 256, 256>>>(midx);
    prep_cent_kernel<<<(M_MODELS * K_CLUST * 32 + 255) / 256, 256>>>(cent);

    fused_kernel<<<M_MODELS * MAXT_G, NTHREADS, SMEM_TOTAL>>>(emb, cent, out);
}

// round 12
// speedup vs baseline: 1.3112x; 1.3112x over previous
#include <cuda_runtime.h>
#include <cuda_bf16.h>
#include <cstdint>

#define T_FRAMES 16384
#define E_DIM    1024
#define M_MODELS 8
#define K_CLUST  512

#define TM   64
#define KBLK 128
#define NSTAGE (E_DIM / KBLK)   // 8
#define MAXT_G 40
#define NTHREADS 512
#define TAU  20.0f
#define CAP  2048

#define STAGE_BYTES 65536   // 32KB fp8-B rows 0-255 swizzled | 32KB dp-B [chunk][col] cols 256-511

// ---- persistent scratch ----
__device__ uint8_t g_cent_pack[M_MODELS * NSTAGE * STAGE_BYTES];   // 4.2MB
__device__ int   g_counts[M_MODELS];
__device__ int   g_rows[M_MODELS * T_FRAMES];
__device__ float g_chalf[M_MODELS * K_CLUST];

// ================= helpers =================
__device__ __forceinline__ uint32_t smem_u32(const void* p) {
    uint32_t a;
    asm("{ .reg .u64 t; cvta.to.shared.u64 t, %1; cvt.u32.u64 %0, t; }" : "=r"(a) : "l"(p));
    return a;
}
__device__ __forceinline__ void bulk_g2s(uint32_t dst, const void* src,
                                         uint32_t bytes, uint32_t mbar) {
    asm volatile(
        "cp.async.bulk.shared::cluster.global.mbarrier::complete_tx::bytes [%0], [%1], %2, [%3];"
        :: "r"(dst), "l"(src), "r"(bytes), "r"(mbar) : "memory");
}
#define BARSYNC() asm volatile("bar.sync 0;" ::: "memory")
#define MBARRIER_INIT(addr, cnt) \
    asm volatile("mbarrier.init.shared.b64 [%0], %1;" :: "r"((uint32_t)(addr)), "r"((uint32_t)(cnt)) : "memory")
#define MBARRIER_EXPECT_TX(addr, bytes) \
    asm volatile("mbarrier.arrive.expect_tx.shared.b64 _, [%0], %1;" \
                 :: "r"((uint32_t)(addr)), "r"((uint32_t)(bytes)) : "memory")
#define MBARRIER_WAIT_PARITY(addr, par) do { \
    uint32_t _mb = (uint32_t)(addr); uint32_t _pr = (uint32_t)(par); uint32_t _done; \
    asm volatile("{\n\t.reg .pred p;\n\t" \
        "mbarrier.try_wait.parity.acquire.cta.shared::cta.b64 p, [%1], %2;\n\t" \
        "selp.b32 %0, 1, 0, p;\n\t}" : "=r"(_done) : "r"(_mb), "r"(_pr) : "memory"); \
    if (!_done) { \
        asm volatile("{\n\t.reg .pred P1;\n\t" \
            "WL_%=:\n\t" \
            "mbarrier.try_wait.parity.acquire.cta.shared::cta.b64 P1, [%0], %1, 0x989680;\n\t" \
            "@P1 bra.uni WD_%=;\n\t" \
            "bra.uni WL_%=;\n\t" \
            "WD_%=:\n\t}" :: "r"(_mb), "r"(_pr) : "memory"); \
    } } while (0)
__device__ __forceinline__ void ldmx4(uint32_t addr, uint32_t& r0, uint32_t& r1,
                                      uint32_t& r2, uint32_t& r3) {
    asm volatile("ldmatrix.sync.aligned.m8n8.x4.shared.b16 {%0,%1,%2,%3}, [%4];"
                 : "=r"(r0), "=r"(r1), "=r"(r2), "=r"(r3) : "r"(addr));
}
__device__ __forceinline__ void mma_fp8(float* c, uint32_t a0, uint32_t a1,
                                        uint32_t a2, uint32_t a3,
                                        uint32_t b0, uint32_t b1) {
    asm volatile(
        "mma.sync.aligned.m16n8k32.row.col.f32.e4m3.e4m3.f32 "
        "{%0,%1,%2,%3}, {%4,%5,%6,%7}, {%8,%9}, {%0,%1,%2,%3};"
        : "+f"(c[0]), "+f"(c[1]), "+f"(c[2]), "+f"(c[3])
        : "r"(a0), "r"(a1), "r"(a2), "r"(a3), "r"(b0), "r"(b1));
}
__device__ __forceinline__ void dp4a(int& acc, uint32_t a, uint32_t b) {
    asm volatile("dp4a.s32.s32 %0, %1, %2, %0;" : "+r"(acc) : "r"(a), "r"(b));
}
__device__ __forceinline__ unsigned int fkey(float f) {
    unsigned u = __float_as_uint(f);
    return (u & 0x80000000u) ? ~u : (u | 0x80000000u);
}
__device__ __forceinline__ float inv_fkey(unsigned k) {
    unsigned u = (k & 0x80000000u) ? (k & 0x7FFFFFFFu) : ~k;
    return __uint_as_float(u);
}
__device__ __forceinline__ uint32_t f4_to_fp8(float4 v) {
    uint32_t p;
    asm("{ .reg .b16 lo, hi;\n\t"
        "cvt.rn.satfinite.e4m3x2.f32 lo, %2, %1;\n\t"
        "cvt.rn.satfinite.e4m3x2.f32 hi, %4, %3;\n\t"
        "mov.b32 %0, {lo, hi}; }"
        : "=r"(p) : "f"(v.x), "f"(v.y), "f"(v.z), "f"(v.w));
    return p;
}
__device__ __forceinline__ uint32_t f4_to_s8(float4 v) {
    int a = __float2int_rn(fminf(fmaxf(v.x * 16.f, -127.f), 127.f));
    int b = __float2int_rn(fminf(fmaxf(v.y * 16.f, -127.f), 127.f));
    int c = __float2int_rn(fminf(fmaxf(v.z * 16.f, -127.f), 127.f));
    int d = __float2int_rn(fminf(fmaxf(v.w * 16.f, -127.f), 127.f));
    return (a & 255) | ((b & 255) << 8) | ((c & 255) << 16) | ((d & 255) << 24);
}

// ================= smem layout (bytes) =================
#define SM_B      0                        // 2 x 64KB
#define SM_A8     131072                   // 2 x 8KB fp8-A swizzled
#define SM_AS8    147456                   // 2 x 8KB s8-A linear
#define SM_CHALF  163840                   // 512 f32
#define SM_ROWIDX 165888                   // 64 int
#define SM_THR    166144                   // 64 f32
#define SM_PMIN   166400                   // 64 u32
#define SM_BEST   166656                   // 64 u64
#define SM_MBAR   167168                   // 2 x 8B
#define SM_CNT    167184                   // int (+pad)
#define SM_CODE   167200                   // 64 int
#define SM_CAND   167456                   // CAP ints
#define SMEM_TOTAL (167456 + CAP * 4 + 32)

// ================= prep kernels =================
__global__ void init_kernel() {
    int t = threadIdx.x;
    if (t < M_MODELS) g_counts[t] = 0;
}

__global__ void bucket_kernel(const int* __restrict__ model_idx) {
    int t = blockIdx.x * blockDim.x + threadIdx.x;
    if (t >= T_FRAMES) return;
    int m = model_idx[t];
    int pos = atomicAdd(&g_counts[m], 1);
    g_rows[m * T_FRAMES + pos] = t;
}

// one warp per centroid row: dual-format pack + chalf (proven correct in R11)
__global__ void prep_cent_kernel(const float* __restrict__ cent) {
    int warp = (blockIdx.x * blockDim.x + threadIdx.x) >> 5;
    int lane = threadIdx.x & 31;
    if (warp >= M_MODELS * K_CLUST) return;
    const int m = warp >> 9;
    const int r = warp & 511;
    const float4* src = reinterpret_cast<const float4*>(cent + (size_t)warp * E_DIM);
    float s = 0.f;
    #pragma unroll
    for (int q = 0; q < NSTAGE; ++q) {
        float4 v = src[lane + 32 * q];
        uint8_t* base = g_cent_pack + ((size_t)(m * NSTAGE + q)) * STAGE_BYTES;
        if (r < 256) {
            uint32_t off = r * 128 + (((lane >> 2) ^ (r & 7)) << 4) + (lane & 3) * 4;
            *reinterpret_cast<uint32_t*>(base + off) = f4_to_fp8(v);
        } else {
            *reinterpret_cast<uint32_t*>(base + 32768 + lane * 1024 + (r - 256) * 4)
                = f4_to_s8(v);
        }
        s += v.x * v.x + v.y * v.y + v.z * v.z + v.w * v.w;
    }
    #pragma unroll
    for (int o = 16; o; o >>= 1) s += __shfl_xor_sync(0xffffffffu, s, o);
    if (lane == 0) g_chalf[warp] = 0.5f * s;
}

// ================= fused hybrid (tensor ∥ dp4a) =================
__global__ __launch_bounds__(NTHREADS, 1)
void fused_kernel(const float* __restrict__ emb, const float* __restrict__ cent,
                  float* __restrict__ out) {
    extern __shared__ char smem[];
    const uint32_t sb = smem_u32(smem);

    const int m   = blockIdx.x / MAXT_G;
    const int mtb = blockIdx.x % MAXT_G;
    const int cnt = g_counts[m];
    const int ntiles = (cnt + TM - 1) / TM;
    const int* rowsm = g_rows + m * T_FRAMES;

    const int tid  = threadIdx.x;
    const int wid  = tid >> 5;
    const int lane = tid & 31;

    int*   rowidx_s = reinterpret_cast<int*>(smem + SM_ROWIDX);
    float* chalf_s  = reinterpret_cast<float*>(smem + SM_CHALF);
    float* thr_s    = reinterpret_cast<float*>(smem + SM_THR);
    unsigned* pmin_s = reinterpret_cast<unsigned*>(smem + SM_PMIN);
    unsigned long long* best_s = reinterpret_cast<unsigned long long*>(smem + SM_BEST);
    int* cnt_s  = reinterpret_cast<int*>(smem + SM_CNT);
    int* code_s = reinterpret_cast<int*>(smem + SM_CODE);
    int* cand_s = reinterpret_cast<int*>(smem + SM_CAND);

    if (tid < 512) chalf_s[tid] = g_chalf[m * K_CLUST + tid];
    if (tid == 0) {
        MBARRIER_INIT(sb + SM_MBAR, 1);
        MBARRIER_INIT(sb + SM_MBAR + 8, 1);
    }
    BARSYNC();

    const uint8_t* bsrc = g_cent_pack + (size_t)m * NSTAGE * STAGE_BYTES;
    const float4* emb4  = reinterpret_cast<const float4*>(emb);
    const float4* cent4 = reinterpret_cast<const float4*>(cent);

    // A producer plan: each thread handles 16 floats/stage (row = tid>>3, 16B chunk af)
    const int ar = tid >> 3, af = tid & 7;
    const uint32_t ad8 = ar * 128 + ((af ^ (ar & 7)) << 4);   // fp8 swizzled 16B
    const uint32_t ads = ar * 128 + af * 16;                  // s8 linear

    uint32_t par0 = 0, par1 = 0;

    for (int mt = mtb; mt < ntiles; mt += MAXT_G) {
        BARSYNC();
        if (tid < TM) {
            int gr = mt * TM + tid;
            rowidx_s[tid] = rowsm[min(gr, cnt - 1)];
            best_s[tid] = 0xFFFFFFFFFFFFFFFFull;
            pmin_s[tid] = 0xFFFFFFFFu;
        }
        if (tid == 0) cnt_s[0] = 0;
        BARSYNC();

        const float4* aS = emb4 + (size_t)rowidx_s[ar] * 256 + af * 4;

        if (wid < 8) {
            // ================= MMA role: cols 0-255 =================
            const int wr = wid >> 1;          // 0..3 : rows wr*16..+16
            const int wc = wid & 1;           // 0..1 : cols wc*128..+128
            const int arow_l = wr * 16 + (lane & 7) + ((lane >> 3) & 1) * 8;
            const int clane  = lane >> 4;
            const int gid = lane >> 2, tig = lane & 3;

            float accf[64];
            #pragma unroll
            for (int i = 0; i < 64; ++i) accf[i] = 0.f;

            if (tid == 0) {
                MBARRIER_EXPECT_TX(sb + SM_MBAR, STAGE_BYTES);
                bulk_g2s(sb + SM_B, bsrc, STAGE_BYTES, sb + SM_MBAR);
            }
            float4 ap0 = aS[0], ap1 = aS[1], ap2 = aS[2], ap3 = aS[3];

            for (int kb = 0; kb < NSTAGE; ++kb) {
                const int buf = kb & 1;
                *reinterpret_cast<uint4*>(smem + SM_A8 + buf * 8192 + ad8) =
                    make_uint4(f4_to_fp8(ap0), f4_to_fp8(ap1), f4_to_fp8(ap2), f4_to_fp8(ap3));
                *reinterpret_cast<uint4*>(smem + SM_AS8 + buf * 8192 + ads) =
                    make_uint4(f4_to_s8(ap0), f4_to_s8(ap1), f4_to_s8(ap2), f4_to_s8(ap3));
                if (kb + 1 < NSTAGE) {
                    const int nb = (kb + 1) & 1;
                    if (tid == 0) {
                        MBARRIER_EXPECT_TX(sb + SM_MBAR + 8 * nb, STAGE_BYTES);
                        bulk_g2s(sb + SM_B + nb * STAGE_BYTES,
                                 bsrc + (size_t)(kb + 1) * STAGE_BYTES,
                                 STAGE_BYTES, sb + SM_MBAR + 8 * nb);
                    }
                    ap0 = aS[(kb + 1) * 32];     ap1 = aS[(kb + 1) * 32 + 1];
                    ap2 = aS[(kb + 1) * 32 + 2]; ap3 = aS[(kb + 1) * 32 + 3];
                }
                if (buf == 0) { MBARRIER_WAIT_PARITY(sb + SM_MBAR, par0); par0 ^= 1; }
                else          { MBARRIER_WAIT_PARITY(sb + SM_MBAR + 8, par1); par1 ^= 1; }
                BARSYNC();

                const uint32_t Ab = sb + SM_A8 + buf * 8192;
                const uint32_t Bb = sb + SM_B + buf * STAGE_BYTES;
                #pragma unroll
                for (int ks = 0; ks < 4; ++ks) {
                    const int cc = ks * 2 + clane;
                    uint32_t a0, a1, a2, a3;
                    ldmx4(Ab + arow_l * 128 + ((cc ^ (arow_l & 7)) << 4), a0, a1, a2, a3);
                    #pragma unroll
                    for (int nb2 = 0; nb2 < 8; ++nb2) {
                        int row = wc * 128 + nb2 * 16 + (lane & 7) + ((lane >> 3) & 1) * 8;
                        uint32_t b0, b1, b2, b3;
                        ldmx4(Bb + row * 128 + ((cc ^ (row & 7)) << 4), b0, b1, b2, b3);
                        mma_fp8(&accf[(nb2 * 2) * 4], a0, a1, a2, a3, b0, b2);
                        mma_fp8(&accf[(nb2 * 2 + 1) * 4], a0, a1, a2, a3, b1, b3);
                    }
                }
                BARSYNC();
            }

            // per-row min
            {
                float v0 = __int_as_float(0x7F800000), v1 = v0;
                #pragma unroll
                for (int n = 0; n < 16; ++n) {
                    int col = wc * 128 + n * 8 + tig * 2;
                    float c0 = chalf_s[col], c1 = chalf_s[col + 1];
                    v0 = fminf(v0, fminf(c0 - accf[n * 4 + 0], c1 - accf[n * 4 + 1]));
                    v1 = fminf(v1, fminf(c0 - accf[n * 4 + 2], c1 - accf[n * 4 + 3]));
                }
                #pragma unroll
                for (int o = 1; o < 4; o <<= 1) {
                    v0 = fminf(v0, __shfl_xor_sync(0xffffffffu, v0, o));
                    v1 = fminf(v1, __shfl_xor_sync(0xffffffffu, v1, o));
                }
                if (tig == 0) {
                    atomicMin(&pmin_s[wr * 16 + gid], fkey(v0));
                    atomicMin(&pmin_s[wr * 16 + gid + 8], fkey(v1));
                }
            }
            BARSYNC();
            if (tid < TM) thr_s[tid] = inv_fkey(pmin_s[tid]) + TAU;
            BARSYNC();
            // candidates
            #pragma unroll
            for (int n = 0; n < 16; ++n) {
                #pragma unroll
                for (int r = 0; r < 4; ++r) {
                    int row = wr * 16 + gid + (r >> 1) * 8;
                    int col = wc * 128 + n * 8 + tig * 2 + (r & 1);
                    float s = chalf_s[col] - accf[n * 4 + r];
                    if (s <= thr_s[row]) {
                        int idx = atomicAdd(cnt_s, 1);
                        if (idx < CAP) cand_s[idx] = (row << 16) | col;
                    }
                }
            }
        } else {
            // ================= dp4a role: cols 256-511 =================
            const int dw = wid - 8;           // 0..7 : frames dw*8..+8
            int acci[64];
            #pragma unroll
            for (int i = 0; i < 64; ++i) acci[i] = 0;

            float4 ap0 = aS[0], ap1 = aS[1], ap2 = aS[2], ap3 = aS[3];

            for (int kb = 0; kb < NSTAGE; ++kb) {
                const int buf = kb & 1;
                *reinterpret_cast<uint4*>(smem + SM_A8 + buf * 8192 + ad8) =
                    make_uint4(f4_to_fp8(ap0), f4_to_fp8(ap1), f4_to_fp8(ap2), f4_to_fp8(ap3));
                *reinterpret_cast<uint4*>(smem + SM_AS8 + buf * 8192 + ads) =
                    make_uint4(f4_to_s8(ap0), f4_to_s8(ap1), f4_to_s8(ap2), f4_to_s8(ap3));
                if (kb + 1 < NSTAGE) {
                    ap0 = aS[(kb + 1) * 32];     ap1 = aS[(kb + 1) * 32 + 1];
                    ap2 = aS[(kb + 1) * 32 + 2]; ap3 = aS[(kb + 1) * 32 + 3];
                }
                if (buf == 0) { MBARRIER_WAIT_PARITY(sb + SM_MBAR, par0); par0 ^= 1; }
                else          { MBARRIER_WAIT_PARITY(sb + SM_MBAR + 8, par1); par1 ^= 1; }
                BARSYNC();

                const char* Abase = smem + SM_AS8 + buf * 8192 + dw * 8 * 128;
                const char* Bd = smem + SM_B + buf * STAGE_BYTES + 32768 + lane * 32;
                #pragma unroll 2
                for (int blk = 0; blk < 16; ++blk) {      // 2 chunks per blk
                    uint2 av[8];
                    #pragma unroll
                    for (int j = 0; j < 8; ++j)
                        av[j] = *reinterpret_cast<const uint2*>(Abase + j * 128 + blk * 8);
                    #pragma unroll
                    for (int c = 0; c < 2; ++c) {
                        const char* bp = Bd + (blk * 2 + c) * 1024;
                        uint4 bv0 = *reinterpret_cast<const uint4*>(bp);
                        uint4 bv1 = *reinterpret_cast<const uint4*>(bp + 16);
                        #pragma unroll
                        for (int j = 0; j < 8; ++j) {
                            uint32_t a = c ? av[j].y : av[j].x;
                            dp4a(acci[j * 8 + 0], a, bv0.x);
                            dp4a(acci[j * 8 + 1], a, bv0.y);
                            dp4a(acci[j * 8 + 2], a, bv0.z);
                            dp4a(acci[j * 8 + 3], a, bv0.w);
                            dp4a(acci[j * 8 + 4], a, bv1.x);
                            dp4a(acci[j * 8 + 5], a, bv1.y);
                            dp4a(acci[j * 8 + 6], a, bv1.z);
                            dp4a(acci[j * 8 + 7], a, bv1.w);
                        }
                    }
                }
                BARSYNC();
            }

            // per-row min over this thread's 8 cols, then warp-reduce per frame
            float ch[8];
            #pragma unroll
            for (int k = 0; k < 8; ++k) ch[k] = chalf_s[256 + lane * 8 + k];
            #pragma unroll
            for (int j = 0; j < 8; ++j) {
                float mv = ch[0] - (float)acci[j * 8] * (1.0f / 256.0f);
                #pragma unroll
                for (int k = 1; k < 8; ++k)
                    mv = fminf(mv, ch[k] - (float)acci[j * 8 + k] * (1.0f / 256.0f));
                #pragma unroll
                for (int o = 16; o; o >>= 1)
                    mv = fminf(mv, __shfl_xor_sync(0xffffffffu, mv, o));
                if (lane == 0) atomicMin(&pmin_s[dw * 8 + j], fkey(mv));
            }
            BARSYNC();
            BARSYNC();   // matches MMA role's thr-compute barrier pair
            #pragma unroll
            for (int j = 0; j < 8; ++j) {
                int row = dw * 8 + j;
                float t = thr_s[row];
                #pragma unroll
                for (int k = 0; k < 8; ++k) {
                    float s = ch[k] - (float)acci[j * 8 + k] * (1.0f / 256.0f);
                    if (s <= t) {
                        int idx = atomicAdd(cnt_s, 1);
                        if (idx < CAP) cand_s[idx] = (row << 16) | (256 + lane * 8 + k);
                    }
                }
            }
        }
        BARSYNC();
        const int ncand = min(cnt_s[0], CAP);

        // ---- exact fp32 rescore (one warp per candidate) ----
        for (int i = wid; i < ncand; i += 16) {
            int rc = cand_s[i];
            int row = rc >> 16, col = rc & 0xFFFF;
            const float4* e4 = emb4 + (size_t)rowidx_s[row] * 256;
            const float4* c4 = cent4 + ((size_t)m * K_CLUST + col) * 256;
            float d = 0.f;
            #pragma unroll
            for (int q = 0; q < 8; ++q) {
                float4 ea = e4[q * 32 + lane];
                float4 ca = c4[q * 32 + lane];
                d += ea.x * ca.x + ea.y * ca.y + ea.z * ca.z + ea.w * ca.w;
            }
            #pragma unroll
            for (int o = 16; o; o >>= 1) d += __shfl_xor_sync(0xffffffffu, d, o);
            if (lane == 0) {
                float s = chalf_s[col] - d;
                unsigned long long key = ((unsigned long long)fkey(s) << 32) | (unsigned)col;
                atomicMin(&best_s[row], key);
            }
        }
        BARSYNC();
        if (tid < TM) code_s[tid] = (int)(unsigned)(best_s[tid] & 0xFFFFFFFFull);
        BARSYNC();

        // ---- write output rows ----
        float4* out4 = reinterpret_cast<float4*>(out);
        for (int idx = tid; idx < TM * 256; idx += NTHREADS) {
            int r = idx >> 8, q = idx & 255;
            if (mt * TM + r < cnt) {
                int frame = rowidx_s[r];
                out4[(size_t)frame * 256 + q] =
                    cent4[((size_t)m * K_CLUST + code_s[r]) * 256 + q];
            }
        }
    }
}

// ================= launch =================
extern "C" void kernel_launch(void* const* d_in, const int* in_sizes, int n_in,
                              void* d_out, int out_size) {
    const float* emb  = (const float*)d_in[0];
    const float* cent = (const float*)d_in[1];
    const int*   midx = (const int*)d_in[2];
    float* out = (float*)d_out;

    cudaFuncSetAttribute(fused_kernel,
                         cudaFuncAttributeMaxDynamicSharedMemorySize, SMEM_TOTAL);

    init_kernel<<<1, 32>>>();
    bucket_kernel<<<(T_FRAMES + 255) / 256, 256>>>(midx);
    prep_cent_kernel<<<(M_MODELS * K_CLUST * 32 + 255) / 256, 256>>>(cent);

    fused_kernel<<<M_MODELS * MAXT_G, NTHREADS, SMEM_TOTAL>>>(emb, cent, out);
}

// round 13
// speedup vs baseline: 1.5480x; 1.1806x over previous
#include <cuda_runtime.h>
#include <cuda_bf16.h>
#include <cstdint>

#define T_FRAMES 16384
#define E_DIM    1024
#define M_MODELS 8
#define K_CLUST  512

#define TM   64
#define TN   512
#define KBLK 128
#define NSTAGE (E_DIM / KBLK)   // 8
#define MAXT_G 40
#define NTHREADS 1024
#define TAU  20.0f
#define CAP  4096

#define B_STAGE_BYTES 65536

// ---- persistent scratch ----
__device__ uint8_t g_cent_s8[M_MODELS * NSTAGE * B_STAGE_BYTES];   // 4.2MB
__device__ int   g_counts[M_MODELS];
__device__ int   g_rows[M_MODELS * T_FRAMES];
__device__ float g_chalf[M_MODELS * K_CLUST];

// ================= helpers =================
__device__ __forceinline__ uint32_t smem_u32(const void* p) {
    uint32_t a;
    asm("{ .reg .u64 t; cvta.to.shared.u64 t, %1; cvt.u32.u64 %0, t; }" : "=r"(a) : "l"(p));
    return a;
}
__device__ __forceinline__ void bulk_g2s(uint32_t dst, const void* src,
                                         uint32_t bytes, uint32_t mbar) {
    asm volatile(
        "cp.async.bulk.shared::cluster.global.mbarrier::complete_tx::bytes [%0], [%1], %2, [%3];"
        :: "r"(dst), "l"(src), "r"(bytes), "r"(mbar) : "memory");
}
#define MBARRIER_INIT(addr, cnt) \
    asm volatile("mbarrier.init.shared.b64 [%0], %1;" :: "r"((uint32_t)(addr)), "r"((uint32_t)(cnt)) : "memory")
#define MBARRIER_EXPECT_TX(addr, bytes) \
    asm volatile("mbarrier.arrive.expect_tx.shared.b64 _, [%0], %1;" \
                 :: "r"((uint32_t)(addr)), "r"((uint32_t)(bytes)) : "memory")
#define MBARRIER_WAIT_PARITY(addr, par) do { \
    uint32_t _mb = (uint32_t)(addr); uint32_t _pr = (uint32_t)(par); uint32_t _done; \
    asm volatile("{\n\t.reg .pred p;\n\t" \
        "mbarrier.try_wait.parity.acquire.cta.shared::cta.b64 p, [%1], %2;\n\t" \
        "selp.b32 %0, 1, 0, p;\n\t}" : "=r"(_done) : "r"(_mb), "r"(_pr) : "memory"); \
    if (!_done) { \
        asm volatile("{\n\t.reg .pred P1;\n\t" \
            "WL_%=:\n\t" \
            "mbarrier.try_wait.parity.acquire.cta.shared::cta.b64 P1, [%0], %1, 0x989680;\n\t" \
            "@P1 bra.uni WD_%=;\n\t" \
            "bra.uni WL_%=;\n\t" \
            "WD_%=:\n\t}" :: "r"(_mb), "r"(_pr) : "memory"); \
    } } while (0)
__device__ __forceinline__ void ldmx4(uint32_t addr, uint32_t& r0, uint32_t& r1,
                                      uint32_t& r2, uint32_t& r3) {
    asm volatile("ldmatrix.sync.aligned.m8n8.x4.shared.b16 {%0,%1,%2,%3}, [%4];"
                 : "=r"(r0), "=r"(r1), "=r"(r2), "=r"(r3) : "r"(addr));
}
__device__ __forceinline__ void mma_fp8(float* c, uint32_t a0, uint32_t a1,
                                        uint32_t a2, uint32_t a3,
                                        uint32_t b0, uint32_t b1) {
    asm volatile(
        "mma.sync.aligned.m16n8k32.row.col.f32.e4m3.e4m3.f32 "
        "{%0,%1,%2,%3}, {%4,%5,%6,%7}, {%8,%9}, {%0,%1,%2,%3};"
        : "+f"(c[0]), "+f"(c[1]), "+f"(c[2]), "+f"(c[3])
        : "r"(a0), "r"(a1), "r"(a2), "r"(a3), "r"(b0), "r"(b1));
}
__device__ __forceinline__ unsigned int fkey(float f) {
    unsigned u = __float_as_uint(f);
    return (u & 0x80000000u) ? ~u : (u | 0x80000000u);
}
__device__ __forceinline__ float inv_fkey(unsigned k) {
    unsigned u = (k & 0x80000000u) ? (k & 0x7FFFFFFFu) : ~k;
    return __uint_as_float(u);
}
__device__ __forceinline__ uint32_t f4_to_fp8(float4 v) {
    uint32_t p;
    asm("{ .reg .b16 lo, hi;\n\t"
        "cvt.rn.satfinite.e4m3x2.f32 lo, %2, %1;\n\t"
        "cvt.rn.satfinite.e4m3x2.f32 hi, %4, %3;\n\t"
        "mov.b32 %0, {lo, hi}; }"
        : "=r"(p) : "f"(v.x), "f"(v.y), "f"(v.z), "f"(v.w));
    return p;
}

// ================= smem layout (bytes) =================
#define SM_B      0                        // 2 x 64KB
#define SM_A      131072                   // 2 x 8KB
#define SM_CHALF  147456                   // 512 f32
#define SM_ROWIDX 149504                   // 64 int
#define SM_THR    149760                   // 64 f32
#define SM_PMIN   150016                   // 64 u32
#define SM_BEST   152064                   // 64 u64
#define SM_MBAR   152576                   // 2 x 8B
#define SM_CNT    152592                   // int (+pad)
#define SM_CODE   152608                   // 64 int
#define SM_CAND   152864                   // CAP ints
#define SMEM_TOTAL (152864 + CAP * 4 + 32)

// ================= prep kernels =================
__global__ void init_kernel() {
    int t = threadIdx.x;
    if (t < M_MODELS) g_counts[t] = 0;
}

__global__ void bucket_kernel(const int* __restrict__ model_idx) {
    int t = blockIdx.x * blockDim.x + threadIdx.x;
    if (t >= T_FRAMES) return;
    int m = model_idx[t];
    int pos = atomicAdd(&g_counts[m], 1);
    g_rows[m * T_FRAMES + pos] = t;
}

// one warp per centroid row: f32 -> e4m3 stage-major pre-swizzled + 0.5*|c|^2
__global__ void prep_cent_kernel(const float* __restrict__ cent) {
    int warp = (blockIdx.x * blockDim.x + threadIdx.x) >> 5;
    int lane = threadIdx.x & 31;
    if (warp >= M_MODELS * K_CLUST) return;
    const int m = warp >> 9;
    const int r = warp & 511;
    const float4* src = reinterpret_cast<const float4*>(cent + (size_t)warp * E_DIM);
    uint8_t* base = g_cent_s8 + (size_t)m * NSTAGE * B_STAGE_BYTES;
    const uint32_t sw16 = ((lane >> 2) ^ (r & 7)) << 4;
    const uint32_t boff = (lane & 3) * 4;
    float s = 0.f;
    #pragma unroll
    for (int q = 0; q < 8; ++q) {
        float4 v = src[lane + 32 * q];
        *reinterpret_cast<uint32_t*>(base + q * B_STAGE_BYTES + r * 128 + sw16 + boff)
            = f4_to_fp8(v);
        s += v.x * v.x + v.y * v.y + v.z * v.z + v.w * v.w;
    }
    #pragma unroll
    for (int o = 16; o; o >>= 1) s += __shfl_xor_sync(0xffffffffu, s, o);
    if (lane == 0) g_chalf[warp] = 0.5f * s;
}

// ================= fused GEMM + argmin + rescore + output =================
__global__ __launch_bounds__(NTHREADS, 1)
void fused_kernel(const float* __restrict__ emb, const float* __restrict__ cent,
                  float* __restrict__ out) {
    extern __shared__ char smem[];
    const uint32_t sb = smem_u32(smem);

    const int m   = blockIdx.x / MAXT_G;
    const int mtb = blockIdx.x % MAXT_G;
    const int cnt = g_counts[m];
    const int ntiles = (cnt + TM - 1) / TM;
    const int* rowsm = g_rows + m * T_FRAMES;

    const int tid  = threadIdx.x;
    const int wid  = tid >> 5;
    const int lane = tid & 31;
    const int wr = wid >> 4;      // 0..1  : 32-frame row group
    const int wc = wid & 15;      // 0..15 : 32-centroid col group

    int*   rowidx_s = reinterpret_cast<int*>(smem + SM_ROWIDX);
    float* chalf_s  = reinterpret_cast<float*>(smem + SM_CHALF);
    float* thr_s    = reinterpret_cast<float*>(smem + SM_THR);
    unsigned* pmin_s = reinterpret_cast<unsigned*>(smem + SM_PMIN);
    unsigned long long* best_s = reinterpret_cast<unsigned long long*>(smem + SM_BEST);
    int* cnt_s  = reinterpret_cast<int*>(smem + SM_CNT);
    int* code_s = reinterpret_cast<int*>(smem + SM_CODE);
    int* cand_s = reinterpret_cast<int*>(smem + SM_CAND);

    if (tid < TN) chalf_s[tid] = g_chalf[m * K_CLUST + tid];
    if (tid == 0) {
        MBARRIER_INIT(sb + SM_MBAR, 1);
        MBARRIER_INIT(sb + SM_MBAR + 8, 1);
    }
    __syncthreads();

    const uint8_t* bsrc = g_cent_s8 + (size_t)m * NSTAGE * B_STAGE_BYTES;
    const float4* emb4  = reinterpret_cast<const float4*>(emb);
    const float4* cent4 = reinterpret_cast<const float4*>(cent);

    const int ar = tid >> 4, af = tid & 15;
    const uint32_t ad = ar * 128 + (((af >> 1) ^ (ar & 7)) << 4) + (af & 1) * 8;

    // fragment row indices
    int arow[2], brow[2];
    #pragma unroll
    for (int i = 0; i < 2; ++i) {
        arow[i] = wr * 32 + i * 16 + (lane & 7) + ((lane >> 3) & 1) * 8;
        brow[i] = wc * 32 + i * 16 + (lane & 7) + ((lane >> 3) & 1) * 8;
    }
    const int clane = lane >> 4;
    const int gid = lane >> 2, tig = lane & 3;

    uint32_t par0 = 0, par1 = 0;

    for (int mt = mtb; mt < ntiles; mt += MAXT_G) {
        __syncthreads();
        if (tid < TM) {
            int gr = mt * TM + tid;
            rowidx_s[tid] = rowsm[min(gr, cnt - 1)];
            best_s[tid] = 0xFFFFFFFFFFFFFFFFull;
            pmin_s[tid] = 0xFFFFFFFFu;
        }
        if (tid == 0) cnt_s[0] = 0;
        __syncthreads();

        const float4* aS = emb4 + (size_t)rowidx_s[ar] * 256 + af * 2;

        float acc[2][4][4];
        #pragma unroll
        for (int mi = 0; mi < 2; ++mi)
            #pragma unroll
            for (int n = 0; n < 4; ++n)
                #pragma unroll
                for (int r = 0; r < 4; ++r) acc[mi][n][r] = 0.f;

        // prologue: stage-0 B bulk, stage-0 A regs
        if (tid == 0) {
            MBARRIER_EXPECT_TX(sb + SM_MBAR, B_STAGE_BYTES);
            bulk_g2s(sb + SM_B, bsrc, B_STAGE_BYTES, sb + SM_MBAR);
        }
        float4 apre0 = aS[0], apre1 = aS[1];

        for (int kb = 0; kb < NSTAGE; ++kb) {
            const int buf = kb & 1;
            const uint32_t Ab = sb + SM_A + buf * 8192;
            const uint32_t Bb = sb + SM_B + buf * 65536;

            // store current A stage (prev readers of this buffer drained at BAR(kb-1))
            *reinterpret_cast<uint2*>(smem + SM_A + buf * 8192 + ad) =
                make_uint2(f4_to_fp8(apre0), f4_to_fp8(apre1));
            if (kb + 1 < NSTAGE) {
                apre0 = aS[(kb + 1) * 32];
                apre1 = aS[(kb + 1) * 32 + 1];
            }
            // wait current B, then the single barrier
            if (buf == 0) { MBARRIER_WAIT_PARITY(sb + SM_MBAR, par0); par0 ^= 1; }
            else          { MBARRIER_WAIT_PARITY(sb + SM_MBAR + 8, par1); par1 ^= 1; }
            __syncthreads();
            // post-BAR: all readers of the other buffer drained -> safe to refill it
            if (kb + 1 < NSTAGE && tid == 0) {
                const int nb = (kb + 1) & 1;
                MBARRIER_EXPECT_TX(sb + SM_MBAR + 8 * nb, B_STAGE_BYTES);
                bulk_g2s(sb + SM_B + nb * 65536, bsrc + (kb + 1) * B_STAGE_BYTES,
                         B_STAGE_BYTES, sb + SM_MBAR + 8 * nb);
            }

            #pragma unroll
            for (int ks = 0; ks < 4; ++ks) {
                const int cc = ks * 2 + clane;
                uint32_t a[2][4];
                #pragma unroll
                for (int mi = 0; mi < 2; ++mi)
                    ldmx4(Ab + arow[mi] * 128 + ((cc ^ (arow[mi] & 7)) << 4),
                          a[mi][0], a[mi][1], a[mi][2], a[mi][3]);
                uint32_t b[2][4];
                #pragma unroll
                for (int nj = 0; nj < 2; ++nj)
                    ldmx4(Bb + brow[nj] * 128 + ((cc ^ (brow[nj] & 7)) << 4),
                          b[nj][0], b[nj][1], b[nj][2], b[nj][3]);
                #pragma unroll
                for (int mi = 0; mi < 2; ++mi)
                    #pragma unroll
                    for (int n = 0; n < 4; ++n)
                        mma_fp8(acc[mi][n], a[mi][0], a[mi][1], a[mi][2], a[mi][3],
                                b[n >> 1][n & 1], b[n >> 1][2 + (n & 1)]);
            }
        }

        // ---- epilogue 1: per-row approx min over this warp's 32 cols ----
        #pragma unroll
        for (int mi = 0; mi < 2; ++mi) {
            float v0 = __int_as_float(0x7F800000), v1 = v0;
            #pragma unroll
            for (int n = 0; n < 4; ++n) {
                int col = wc * 32 + n * 8 + tig * 2;
                float c0 = chalf_s[col], c1 = chalf_s[col + 1];
                v0 = fminf(v0, fminf(c0 - acc[mi][n][0], c1 - acc[mi][n][1]));
                v1 = fminf(v1, fminf(c0 - acc[mi][n][2], c1 - acc[mi][n][3]));
            }
            #pragma unroll
            for (int o = 1; o < 4; o <<= 1) {
                v0 = fminf(v0, __shfl_xor_sync(0xffffffffu, v0, o));
                v1 = fminf(v1, __shfl_xor_sync(0xffffffffu, v1, o));
            }
            if (tig == 0) {
                atomicMin(&pmin_s[wr * 32 + mi * 16 + gid], fkey(v0));
                atomicMin(&pmin_s[wr * 32 + mi * 16 + gid + 8], fkey(v1));
            }
        }
        __syncthreads();
        if (tid < TM) thr_s[tid] = inv_fkey(pmin_s[tid]) + TAU;
        __syncthreads();

        // ---- epilogue 2: collect candidates ----
        #pragma unroll
        for (int mi = 0; mi < 2; ++mi) {
            #pragma unroll
            for (int n = 0; n < 4; ++n) {
                #pragma unroll
                for (int r = 0; r < 4; ++r) {
                    int row = wr * 32 + mi * 16 + gid + (r >> 1) * 8;
                    int col = wc * 32 + n * 8 + tig * 2 + (r & 1);
                    float s = chalf_s[col] - acc[mi][n][r];
                    if (s <= thr_s[row]) {
                        int idx = atomicAdd(cnt_s, 1);
                        if (idx < CAP) cand_s[idx] = (row << 16) | col;
                    }
                }
            }
        }
        __syncthreads();
        const int ncand = min(cnt_s[0], CAP);

        // ---- epilogue 3: exact fp32 rescore (one warp per candidate) ----
        for (int i = wid; i < ncand; i += 32) {
            int rc = cand_s[i];
            int row = rc >> 16, col = rc & 0xFFFF;
            const float4* e4 = emb4 + (size_t)rowidx_s[row] * 256;
            const float4* c4 = cent4 + ((size_t)m * K_CLUST + col) * 256;
            float d = 0.f;
            #pragma unroll
            for (int q = 0; q < 8; ++q) {
                float4 ea = e4[q * 32 + lane];
                float4 ca = c4[q * 32 + lane];
                d += ea.x * ca.x + ea.y * ca.y + ea.z * ca.z + ea.w * ca.w;
            }
            #pragma unroll
            for (int o = 16; o; o >>= 1) d += __shfl_xor_sync(0xffffffffu, d, o);
            if (lane == 0) {
                float s = chalf_s[col] - d;
                unsigned long long key = ((unsigned long long)fkey(s) << 32) | (unsigned)col;
                atomicMin(&best_s[row], key);   // ties -> smaller col (first-min)
            }
        }
        __syncthreads();
        if (tid < TM) code_s[tid] = (int)(unsigned)(best_s[tid] & 0xFFFFFFFFull);
        __syncthreads();

        // ---- epilogue 4: write output rows ----
        float4* out4 = reinterpret_cast<float4*>(out);
        for (int idx = tid; idx < TM * 256; idx += NTHREADS) {
            int r = idx >> 8, q = idx & 255;
            if (mt * TM + r < cnt) {
                int frame = rowidx_s[r];
                out4[(size_t)frame * 256 + q] =
                    cent4[((size_t)m * K_CLUST + code_s[r]) * 256 + q];
            }
        }
    }
}

// ================= launch =================
extern "C" void kernel_launch(void* const* d_in, const int* in_sizes, int n_in,
                              void* d_out, int out_size) {
    const float* emb  = (const float*)d_in[0];
    const float* cent = (const float*)d_in[1];
    const int*   midx = (const int*)d_in[2];
    float* out = (float*)d_out;

    cudaFuncSetAttribute(fused_kernel,
                         cudaFuncAttributeMaxDynamicSharedMemorySize, SMEM_TOTAL);

    init_kernel<<<1, 32>>>();
    bucket_kernel<<<(T_FRAMES + 255) / 256, 256>>>(midx);
    prep_cent_kernel<<<(M_MODELS * K_CLUST * 32 + 255) / 256, 256>>>(cent);

    fused_kernel<<<M_MODELS * MAXT_G, NTHREADS, SMEM_TOTAL>>>(emb, cent, out);
}

// round 14
// speedup vs baseline: 1.8459x; 1.1924x over previous
#include <cuda_runtime.h>
#include <cuda_bf16.h>
#include <cstdint>

#define T_FRAMES 16384
#define E_DIM    1024
#define M_MODELS 8
#define K_CLUST  512

#define TM   64
#define TN   512
#define KBLK 128
#define NSTAGE (E_DIM / KBLK)   // 8
#define MAXT_G 34               // grid tiles per model (stride loop guards overflow)
#define NTHREADS 1024
#define TAU  20.0f
#define CAP  4096

#define B_STAGE_BYTES 65536

// ---- persistent scratch ----
__device__ uint8_t g_cent_s8[M_MODELS * NSTAGE * B_STAGE_BYTES];   // 4.2MB
__device__ int   g_counts[M_MODELS];
__device__ int   g_rows[M_MODELS * T_FRAMES];
__device__ float g_chalf[M_MODELS * K_CLUST];

// ================= helpers =================
__device__ __forceinline__ uint32_t smem_u32(const void* p) {
    uint32_t a;
    asm("{ .reg .u64 t; cvta.to.shared.u64 t, %1; cvt.u32.u64 %0, t; }" : "=r"(a) : "l"(p));
    return a;
}
__device__ __forceinline__ void bulk_g2s(uint32_t dst, const void* src,
                                         uint32_t bytes, uint32_t mbar) {
    asm volatile(
        "cp.async.bulk.shared::cluster.global.mbarrier::complete_tx::bytes [%0], [%1], %2, [%3];"
        :: "r"(dst), "l"(src), "r"(bytes), "r"(mbar) : "memory");
}
#define MBARRIER_INIT(addr, cnt) \
    asm volatile("mbarrier.init.shared.b64 [%0], %1;" :: "r"((uint32_t)(addr)), "r"((uint32_t)(cnt)) : "memory")
#define MBARRIER_EXPECT_TX(addr, bytes) \
    asm volatile("mbarrier.arrive.expect_tx.shared.b64 _, [%0], %1;" \
                 :: "r"((uint32_t)(addr)), "r"((uint32_t)(bytes)) : "memory")
#define MBARRIER_WAIT_PARITY(addr, par) do { \
    uint32_t _mb = (uint32_t)(addr); uint32_t _pr = (uint32_t)(par); uint32_t _done; \
    asm volatile("{\n\t.reg .pred p;\n\t" \
        "mbarrier.try_wait.parity.acquire.cta.shared::cta.b64 p, [%1], %2;\n\t" \
        "selp.b32 %0, 1, 0, p;\n\t}" : "=r"(_done) : "r"(_mb), "r"(_pr) : "memory"); \
    if (!_done) { \
        asm volatile("{\n\t.reg .pred P1;\n\t" \
            "WL_%=:\n\t" \
            "mbarrier.try_wait.parity.acquire.cta.shared::cta.b64 P1, [%0], %1, 0x989680;\n\t" \
            "@P1 bra.uni WD_%=;\n\t" \
            "bra.uni WL_%=;\n\t" \
            "WD_%=:\n\t}" :: "r"(_mb), "r"(_pr) : "memory"); \
    } } while (0)
__device__ __forceinline__ void ldmx4(uint32_t addr, uint32_t& r0, uint32_t& r1,
                                      uint32_t& r2, uint32_t& r3) {
    asm volatile("ldmatrix.sync.aligned.m8n8.x4.shared.b16 {%0,%1,%2,%3}, [%4];"
                 : "=r"(r0), "=r"(r1), "=r"(r2), "=r"(r3) : "r"(addr));
}
__device__ __forceinline__ void mma_fp8(float* c, uint32_t a0, uint32_t a1,
                                        uint32_t a2, uint32_t a3,
                                        uint32_t b0, uint32_t b1) {
    asm volatile(
        "mma.sync.aligned.m16n8k32.row.col.f32.e4m3.e4m3.f32 "
        "{%0,%1,%2,%3}, {%4,%5,%6,%7}, {%8,%9}, {%0,%1,%2,%3};"
        : "+f"(c[0]), "+f"(c[1]), "+f"(c[2]), "+f"(c[3])
        : "r"(a0), "r"(a1), "r"(a2), "r"(a3), "r"(b0), "r"(b1));
}
__device__ __forceinline__ unsigned int fkey(float f) {
    unsigned u = __float_as_uint(f);
    return (u & 0x80000000u) ? ~u : (u | 0x80000000u);
}
__device__ __forceinline__ float inv_fkey(unsigned k) {
    unsigned u = (k & 0x80000000u) ? (k & 0x7FFFFFFFu) : ~k;
    return __uint_as_float(u);
}
__device__ __forceinline__ uint32_t f4_to_fp8(float4 v) {
    uint32_t p;
    asm("{ .reg .b16 lo, hi;\n\t"
        "cvt.rn.satfinite.e4m3x2.f32 lo, %2, %1;\n\t"
        "cvt.rn.satfinite.e4m3x2.f32 hi, %4, %3;\n\t"
        "mov.b32 %0, {lo, hi}; }"
        : "=r"(p) : "f"(v.x), "f"(v.y), "f"(v.z), "f"(v.w));
    return p;
}

// ================= smem layout (bytes) =================
#define SM_B      0                        // 2 x 64KB
#define SM_A      131072                   // 2 x 8KB
#define SM_CHALF  147456                   // 512 f32
#define SM_ROWIDX 149504                   // 64 int
#define SM_THR    149760                   // 64 f32
#define SM_PMIN   150016                   // 64 x 8 f32
#define SM_BEST   152064                   // 64 u64
#define SM_MBAR   152576                   // 2 x 8B
#define SM_CNT    152592                   // int (+pad)
#define SM_CODE   152608                   // 64 int
#define SM_CAND   152864                   // CAP ints
#define SMEM_TOTAL (152864 + CAP * 4 + 32) // ~169KB -> 1 CTA/SM

// ================= prep kernels =================
__global__ void init_kernel() {
    int t = threadIdx.x;
    if (t < M_MODELS) g_counts[t] = 0;
}

// fused: bucket (first 16384 threads) + cent pack/chalf (one warp per row)
__global__ void prep_kernel(const float* __restrict__ cent,
                            const int* __restrict__ model_idx) {
    int gt = blockIdx.x * blockDim.x + threadIdx.x;
    if (gt < T_FRAMES) {
        int mm = model_idx[gt];
        int pos = atomicAdd(&g_counts[mm], 1);
        g_rows[mm * T_FRAMES + pos] = gt;
    }
    int warp = gt >> 5;
    int lane = threadIdx.x & 31;
    if (warp >= M_MODELS * K_CLUST) return;
    const int m = warp >> 9;
    const int r = warp & 511;
    const float4* src = reinterpret_cast<const float4*>(cent + (size_t)warp * E_DIM);
    uint8_t* base = g_cent_s8 + (size_t)m * NSTAGE * B_STAGE_BYTES;
    const uint32_t sw16 = ((lane >> 2) ^ (r & 7)) << 4;
    const uint32_t boff = (lane & 3) * 4;
    float s = 0.f;
    #pragma unroll
    for (int q = 0; q < 8; ++q) {
        float4 v = src[lane + 32 * q];
        *reinterpret_cast<uint32_t*>(base + q * B_STAGE_BYTES + r * 128 + sw16 + boff)
            = f4_to_fp8(v);
        s += v.x * v.x + v.y * v.y + v.z * v.z + v.w * v.w;
    }
    #pragma unroll
    for (int o = 16; o; o >>= 1) s += __shfl_xor_sync(0xffffffffu, s, o);
    if (lane == 0) g_chalf[warp] = 0.5f * s;
}

// ================= fused GEMM + argmin + rescore + output =================
// grid.x = M_MODELS * MAXT_G : m = bx / MAXT_G, tile-stride loop over mt
__global__ __launch_bounds__(NTHREADS, 1)
void fused_kernel(const float* __restrict__ emb, const float* __restrict__ cent,
                  float* __restrict__ out) {
    extern __shared__ char smem[];
    const uint32_t sb = smem_u32(smem);

    const int m   = blockIdx.x / MAXT_G;
    const int mtb = blockIdx.x % MAXT_G;
    const int cnt = g_counts[m];
    const int ntiles = (cnt + TM - 1) / TM;
    const int* rowsm = g_rows + m * T_FRAMES;

    const int tid  = threadIdx.x;
    const int wid  = tid >> 5;
    const int lane = tid & 31;
    const int wr = wid >> 3;      // 0..3 : 16-frame row group
    const int wc = wid & 7;       // 0..7 : 64-centroid col group

    int*   rowidx_s = reinterpret_cast<int*>(smem + SM_ROWIDX);
    float* chalf_s  = reinterpret_cast<float*>(smem + SM_CHALF);
    float* thr_s    = reinterpret_cast<float*>(smem + SM_THR);
    float* pmin_s   = reinterpret_cast<float*>(smem + SM_PMIN);
    unsigned long long* best_s = reinterpret_cast<unsigned long long*>(smem + SM_BEST);
    int* cnt_s  = reinterpret_cast<int*>(smem + SM_CNT);
    int* code_s = reinterpret_cast<int*>(smem + SM_CODE);
    int* cand_s = reinterpret_cast<int*>(smem + SM_CAND);

    if (tid < TN) chalf_s[tid] = g_chalf[m * K_CLUST + tid];
    if (tid == 0) {
        MBARRIER_INIT(sb + SM_MBAR, 1);
        MBARRIER_INIT(sb + SM_MBAR + 8, 1);
    }
    __syncthreads();

    const uint8_t* bsrc = g_cent_s8 + (size_t)m * NSTAGE * B_STAGE_BYTES;
    const float4* emb4  = reinterpret_cast<const float4*>(emb);
    const float4* cent4 = reinterpret_cast<const float4*>(cent);

    const int ar = tid >> 4, af = tid & 15;
    const uint32_t ad = ar * 128 + (((af >> 1) ^ (ar & 7)) << 4) + (af & 1) * 8;
    const int arow_l = wr * 16 + (lane & 7) + ((lane >> 3) & 1) * 8;
    const int brow_l = wc * 64 + (lane & 7) + ((lane >> 3) & 1) * 8;
    const int clane  = lane >> 4;
    const int gid = lane >> 2, tig = lane & 3;

    uint32_t par[2] = {0, 0};

    for (int mt = mtb; mt < ntiles; mt += MAXT_G) {
        __syncthreads();   // previous tile's epilogue readers done
        if (tid < TM) {
            int gr = mt * TM + tid;
            rowidx_s[tid] = rowsm[min(gr, cnt - 1)];
            best_s[tid] = 0xFFFFFFFFFFFFFFFFull;
        }
        if (tid == 0) cnt_s[0] = 0;
        __syncthreads();

        const float4* aS = emb4 + (size_t)rowidx_s[ar] * 256 + af * 2;

        float acc[8][4];
        #pragma unroll
        for (int n = 0; n < 8; ++n)
            #pragma unroll
            for (int r = 0; r < 4; ++r) acc[n][r] = 0.f;

        // prologue: stage-0 B bulk + stage-0 A regs
        if (tid == 0) {
            MBARRIER_EXPECT_TX(sb + SM_MBAR, B_STAGE_BYTES);
            bulk_g2s(sb + SM_B, bsrc, B_STAGE_BYTES, sb + SM_MBAR);
        }
        float4 apre0 = aS[0], apre1 = aS[1];

        for (int kb = 0; kb < NSTAGE; ++kb) {
            const int buf = kb & 1;
            const uint32_t Ab = sb + SM_A + buf * 8192;
            const uint32_t Bb = sb + SM_B + buf * 65536;
            // store current A stage (prev readers of this A buffer drained at BAR(kb-1))
            *reinterpret_cast<uint2*>(smem + SM_A + buf * 8192 + ad) =
                make_uint2(f4_to_fp8(apre0), f4_to_fp8(apre1));
            if (kb + 1 < NSTAGE) {
                apre0 = aS[(kb + 1) * 32];
                apre1 = aS[(kb + 1) * 32 + 1];
            }
            // wait current B, single barrier, then refill the drained buffer
            if (buf == 0) { MBARRIER_WAIT_PARITY(sb + SM_MBAR, par[0]); par[0] ^= 1; }
            else          { MBARRIER_WAIT_PARITY(sb + SM_MBAR + 8, par[1]); par[1] ^= 1; }
            __syncthreads();
            if (kb + 1 < NSTAGE && tid == 0) {
                const int nb = (kb + 1) & 1;
                MBARRIER_EXPECT_TX(sb + SM_MBAR + 8 * nb, B_STAGE_BYTES);
                bulk_g2s(sb + SM_B + nb * 65536, bsrc + (kb + 1) * B_STAGE_BYTES,
                         B_STAGE_BYTES, sb + SM_MBAR + 8 * nb);
            }

            #pragma unroll
            for (int ks = 0; ks < 4; ++ks) {      // k32 slice within 128-fp8 stage
                const int cc = ks * 2 + clane;
                uint32_t a0, a1, a2, a3;
                ldmx4(Ab + arow_l * 128 + ((cc ^ (arow_l & 7)) << 4), a0, a1, a2, a3);
                #pragma unroll
                for (int nh = 0; nh < 2; ++nh) {
                    uint32_t b[2][4];
                    #pragma unroll
                    for (int nj = 0; nj < 2; ++nj) {
                        int row = brow_l + nh * 32 + nj * 16;
                        ldmx4(Bb + row * 128 + ((cc ^ (row & 7)) << 4),
                              b[nj][0], b[nj][1], b[nj][2], b[nj][3]);
                    }
                    #pragma unroll
                    for (int n = 0; n < 4; ++n)
                        mma_fp8(acc[nh * 4 + n], a0, a1, a2, a3,
                                b[n >> 1][n & 1], b[n >> 1][2 + (n & 1)]);
                }
            }
        }

        // ---- epilogue 1: per-row approx min over this warp's 64 cols ----
        {
            float v0 = __int_as_float(0x7F800000), v1 = v0;
            #pragma unroll
            for (int n = 0; n < 8; ++n) {
                int col = wc * 64 + n * 8 + tig * 2;
                float c0 = chalf_s[col], c1 = chalf_s[col + 1];
                v0 = fminf(v0, fminf(c0 - acc[n][0], c1 - acc[n][1]));
                v1 = fminf(v1, fminf(c0 - acc[n][2], c1 - acc[n][3]));
            }
            #pragma unroll
            for (int o = 1; o < 4; o <<= 1) {
                v0 = fminf(v0, __shfl_xor_sync(0xffffffffu, v0, o));
                v1 = fminf(v1, __shfl_xor_sync(0xffffffffu, v1, o));
            }
            if (tig == 0) {
                pmin_s[(wr * 16 + gid) * 8 + wc] = v0;
                pmin_s[(wr * 16 + gid + 8) * 8 + wc] = v1;
            }
        }
        __syncthreads();
        if (tid < TM) {
            float v = pmin_s[tid * 8];
            #pragma unroll
            for (int w = 1; w < 8; ++w) v = fminf(v, pmin_s[tid * 8 + w]);
            thr_s[tid] = v + TAU;
        }
        __syncthreads();

        // ---- epilogue 2: collect candidates ----
        #pragma unroll
        for (int n = 0; n < 8; ++n) {
            #pragma unroll
            for (int r = 0; r < 4; ++r) {
                int row = wr * 16 + gid + (r >> 1) * 8;
                int col = wc * 64 + n * 8 + tig * 2 + (r & 1);
                float s = chalf_s[col] - acc[n][r];
                if (s <= thr_s[row]) {
                    int idx = atomicAdd(cnt_s, 1);
                    if (idx < CAP) cand_s[idx] = (row << 16) | col;
                }
            }
        }
        __syncthreads();
        const int ncand = min(cnt_s[0], CAP);

        // ---- epilogue 3: exact fp32 rescore (one warp per candidate) ----
        for (int i = wid; i < ncand; i += 32) {
            int rc = cand_s[i];
            int row = rc >> 16, col = rc & 0xFFFF;
            const float4* e4 = emb4 + (size_t)rowidx_s[row] * 256;
            const float4* c4 = cent4 + ((size_t)m * K_CLUST + col) * 256;
            float d = 0.f;
            #pragma unroll
            for (int q = 0; q < 8; ++q) {
                float4 ea = e4[q * 32 + lane];
                float4 ca = c4[q * 32 + lane];
                d += ea.x * ca.x + ea.y * ca.y + ea.z * ca.z + ea.w * ca.w;
            }
            #pragma unroll
            for (int o = 16; o; o >>= 1) d += __shfl_xor_sync(0xffffffffu, d, o);
            if (lane == 0) {
                float s = chalf_s[col] - d;   // exact fp32 score
                unsigned long long key = ((unsigned long long)fkey(s) << 32) | (unsigned)col;
                atomicMin(&best_s[row], key); // ties -> smaller col (first-min)
            }
        }
        __syncthreads();
        if (tid < TM) code_s[tid] = (int)(unsigned)(best_s[tid] & 0xFFFFFFFFull);
        __syncthreads();

        // ---- epilogue 4: write output rows directly ----
        float4* out4 = reinterpret_cast<float4*>(out);
        for (int idx = tid; idx < TM * 256; idx += NTHREADS) {
            int r = idx >> 8, q = idx & 255;
            if (mt * TM + r < cnt) {
                int frame = rowidx_s[r];
                out4[(size_t)frame * 256 + q] =
                    cent4[((size_t)m * K_CLUST + code_s[r]) * 256 + q];
            }
        }
    }
}

// ================= launch =================
extern "C" void kernel_launch(void* const* d_in, const int* in_sizes, int n_in,
                              void* d_out, int out_size) {
    const float* emb  = (const float*)d_in[0];
    const float* cent = (const float*)d_in[1];
    const int*   midx = (const int*)d_in[2];
    float* out = (float*)d_out;

    cudaFuncSetAttribute(fused_kernel,
                         cudaFuncAttributeMaxDynamicSharedMemorySize, SMEM_TOTAL);

    init_kernel<<<1, 32>>>();
    prep_kernel<<<(M_MODELS * K_CLUST * 32 + 255) / 256, 256>>>(cent, midx);

    fused_kernel<<<M_MODELS * MAXT_G, NTHREADS, SMEM_TOTAL>>>(emb, cent, out);
}